// round 16
// baseline (speedup 1.0000x reference)
#include <cuda_runtime.h>
#include <cuda_bf16.h>
#include <cstdint>

#define B_Q   1024
#define N_C   131072
#define DIM   256
#define DB    512
#define CTX   96

// ---------------- device scratch (no dynamic allocations allowed) ----------------
__device__ float          g_cnorm[N_C];
__device__ __nv_bfloat16  g_negdist[(size_t)B_Q * N_C];     // 256 MB
__device__ unsigned short g_cmax[(size_t)B_Q * 2048];       // 4 MB: per-row per-64-chunk max key
__device__ __nv_bfloat16  g_CKb[(size_t)N_C * DIM];         // 67 MB
__device__ __nv_bfloat16  g_Kb[B_Q * DIM];                  // 512 KB
__device__ float          g_a[B_Q * DB];                    // 2 MB: a[q][e] = k_q.w1_e + b1_e
__device__ int            g_idx[B_Q * CTX];

// ================= helpers (legacy tensor path only — NO tcgen05) =================
__device__ __forceinline__ unsigned smem_u32(const void* p) {
    return (unsigned)__cvta_generic_to_shared(p);
}
__device__ __forceinline__ void cp16(void* sdst, const void* gsrc) {
    asm volatile("cp.async.cg.shared.global [%0], [%1], 16;\n"
                 :: "r"(smem_u32(sdst)), "l"(gsrc) : "memory");
}
#define CP_COMMIT() asm volatile("cp.async.commit_group;\n" ::: "memory")
#define CP_WAIT(n)  asm volatile("cp.async.wait_group %0;\n" :: "n"(n) : "memory")

__device__ __forceinline__ void mma16816(float* c, const unsigned* a, const unsigned* b) {
    asm volatile(
        "mma.sync.aligned.m16n8k16.row.col.f32.bf16.bf16.f32 "
        "{%0,%1,%2,%3}, {%4,%5,%6,%7}, {%8,%9}, {%0,%1,%2,%3};\n"
        : "+f"(c[0]), "+f"(c[1]), "+f"(c[2]), "+f"(c[3])
        : "r"(a[0]), "r"(a[1]), "r"(a[2]), "r"(a[3]), "r"(b[0]), "r"(b[1]));
}
__device__ __forceinline__ void mma_tf32(float* c, const unsigned* a, const unsigned* b) {
    asm volatile(
        "mma.sync.aligned.m16n8k8.row.col.f32.tf32.tf32.f32 "
        "{%0,%1,%2,%3}, {%4,%5,%6,%7}, {%8,%9}, {%0,%1,%2,%3};\n"
        : "+f"(c[0]), "+f"(c[1]), "+f"(c[2]), "+f"(c[3])
        : "r"(a[0]), "r"(a[1]), "r"(a[2]), "r"(a[3]), "r"(b[0]), "r"(b[1]));
}
__device__ __forceinline__ void ldsm_x4(unsigned* r, const __nv_bfloat16* p) {
    unsigned addr = smem_u32(p);
    asm volatile("ldmatrix.sync.aligned.m8n8.x4.shared.b16 {%0,%1,%2,%3}, [%4];\n"
                 : "=r"(r[0]), "=r"(r[1]), "=r"(r[2]), "=r"(r[3]) : "r"(addr));
}
__device__ __forceinline__ unsigned fkey16(unsigned h) {
    return (h & 0x8000u) ? (~h & 0xffffu) : (h | 0x8000u);  // monotonic in bf16 value
}

// ---------------- kernel 1: fp32 -> bf16 convert (+ optional norms) ----------------
template <bool WITH_NORM>
__global__ void conv_kernel(const float* __restrict__ src, __nv_bfloat16* __restrict__ dst) {
    int row  = blockIdx.x * 8 + (threadIdx.x >> 5);
    int lane = threadIdx.x & 31;
    const float4* p = (const float4*)(src + (size_t)row * DIM);
    float4 v0 = p[lane];
    float4 v1 = p[lane + 32];

    uint2* d2 = (uint2*)(dst + (size_t)row * DIM);
    __nv_bfloat162 a0 = __floats2bfloat162_rn(v0.x, v0.y);
    __nv_bfloat162 a1 = __floats2bfloat162_rn(v0.z, v0.w);
    __nv_bfloat162 a2 = __floats2bfloat162_rn(v1.x, v1.y);
    __nv_bfloat162 a3 = __floats2bfloat162_rn(v1.z, v1.w);
    d2[lane]      = make_uint2(*(unsigned*)&a0, *(unsigned*)&a1);
    d2[lane + 32] = make_uint2(*(unsigned*)&a2, *(unsigned*)&a3);

    if (WITH_NORM) {
        float s = v0.x*v0.x + v0.y*v0.y + v0.z*v0.z + v0.w*v0.w
                + v1.x*v1.x + v1.y*v1.y + v1.z*v1.z + v1.w*v1.w;
        #pragma unroll
        for (int off = 16; off > 0; off >>= 1) s += __shfl_xor_sync(0xffffffffu, s, off);
        if (lane == 0) g_cnorm[row] = s;
    }
}

// ---------------- kernel 1b: a[q][e] = k_q . w1_e + b1_e  (fp32, tiny GEMM) ----------------
__global__ __launch_bounds__(256)
void aker(const float* __restrict__ K, const float* __restrict__ W1,
          const float* __restrict__ B1) {
    __shared__ float Asm[16][65];
    __shared__ float Bsm[16][65];
    int tid = threadIdx.x;
    int tx = tid & 15, ty = tid >> 4;
    int bm0 = blockIdx.x * 64;
    int bn0 = blockIdx.y * 64;

    float acc[4][4];
    #pragma unroll
    for (int i = 0; i < 4; i++)
        #pragma unroll
        for (int j = 0; j < 4; j++) acc[i][j] = 0.f;

    int m  = tid >> 2;
    int k4 = (tid & 3) * 4;
    for (int kk = 0; kk < DIM; kk += 16) {
        float4 va = *(const float4*)(K  + (size_t)(bm0 + m) * DIM + kk + k4);
        Asm[k4][m] = va.x; Asm[k4+1][m] = va.y; Asm[k4+2][m] = va.z; Asm[k4+3][m] = va.w;
        float4 vb = *(const float4*)(W1 + (size_t)(bn0 + m) * DIM + kk + k4);
        Bsm[k4][m] = vb.x; Bsm[k4+1][m] = vb.y; Bsm[k4+2][m] = vb.z; Bsm[k4+3][m] = vb.w;
        __syncthreads();
        #pragma unroll
        for (int k = 0; k < 16; k++) {
            float a[4], b[4];
            #pragma unroll
            for (int i = 0; i < 4; i++) a[i] = Asm[k][ty*4 + i];
            #pragma unroll
            for (int j = 0; j < 4; j++) b[j] = Bsm[k][tx*4 + j];
            #pragma unroll
            for (int i = 0; i < 4; i++)
                #pragma unroll
                for (int j = 0; j < 4; j++) acc[i][j] += a[i] * b[j];
        }
        __syncthreads();
    }
    #pragma unroll
    for (int i = 0; i < 4; i++)
        #pragma unroll
        for (int j = 0; j < 4; j++)
            g_a[(size_t)(bm0 + ty*4 + i) * DB + bn0 + tx*4 + j] = acc[i][j] + B1[bn0 + tx*4 + j];
}

// ---------------- kernel 2: neg_dist (bf16 HMMA) + per-chunk max epilogue ----------------
#define SMS 40   // smem row stride in bf16 (80 B): conflict-free ldmatrix
__global__ __launch_bounds__(256, 2)
void dist_kernel(const __nv_bfloat16* __restrict__ Kb, const __nv_bfloat16* __restrict__ CKb) {
    __shared__ __align__(16) __nv_bfloat16 As[3][128 * SMS];
    __shared__ __align__(16) __nv_bfloat16 Bs[3][128 * SMS];
    __shared__ float cm[128][4];
    int tid  = threadIdx.x;
    int warp = tid >> 5, lane = tid & 31;
    int wm = warp >> 2, wn = warp & 3;       // 2 x 4 warps; warp tile 64(M) x 32(N)
    int bm0 = blockIdx.x * 128, bn0 = blockIdx.y * 128;

    float acc[4][4][4];
    #pragma unroll
    for (int i = 0; i < 4; i++)
        #pragma unroll
        for (int j = 0; j < 4; j++)
            #pragma unroll
            for (int r = 0; r < 4; r++) acc[i][j][r] = 0.f;

    auto load_chunk = [&](int kc, int b) {
        #pragma unroll
        for (int u = 0; u < 2; u++) {
            int t = u * 256 + tid;
            int r = t >> 2, c = (t & 3) * 8;
            cp16(As[b] + r * SMS + c, Kb  + (size_t)(bm0 + r) * DIM + kc * 32 + c);
            cp16(Bs[b] + r * SMS + c, CKb + (size_t)(bn0 + r) * DIM + kc * 32 + c);
        }
    };

    load_chunk(0, 0); CP_COMMIT();
    load_chunk(1, 1); CP_COMMIT();

    for (int kc = 0; kc < 8; kc++) {
        if (kc < 7) CP_WAIT(1); else CP_WAIT(0);
        __syncthreads();
        if (kc + 2 < 8) {
            load_chunk(kc + 2, (kc + 2) % 3);
            CP_COMMIT();
        }
        const __nv_bfloat16* Ac = As[kc % 3];
        const __nv_bfloat16* Bc = Bs[kc % 3];
        #pragma unroll
        for (int s = 0; s < 2; s++) {
            unsigned af[4][4], bf[2][4];
            #pragma unroll
            for (int i = 0; i < 4; i++) {
                int row = wm * 64 + i * 16 + (lane & 15);
                int col = s * 16 + (lane >> 4) * 8;
                ldsm_x4(af[i], Ac + row * SMS + col);
            }
            #pragma unroll
            for (int p = 0; p < 2; p++) {
                int mi   = lane >> 3;
                int nrow = wn * 32 + p * 16 + (mi >> 1) * 8 + (lane & 7);
                int kcol = s * 16 + (mi & 1) * 8;
                ldsm_x4(bf[p], Bc + nrow * SMS + kcol);
            }
            #pragma unroll
            for (int i = 0; i < 4; i++)
                #pragma unroll
                for (int j = 0; j < 4; j++)
                    mma16816(acc[i][j], af[i], &bf[j >> 1][(j & 1) * 2]);
        }
        __syncthreads();
    }

    float cn[4][2];
    #pragma unroll
    for (int j = 0; j < 4; j++) {
        int n = bn0 + wn * 32 + j * 8 + (lane & 3) * 2;
        cn[j][0] = g_cnorm[n]; cn[j][1] = g_cnorm[n + 1];
    }
    #pragma unroll
    for (int i = 0; i < 4; i++) {
        int row0 = bm0 + wm * 64 + i * 16 + (lane >> 2);
        float m0 = -3.4e38f, m8 = -3.4e38f;
        #pragma unroll
        for (int j = 0; j < 4; j++) {
            int n = bn0 + wn * 32 + j * 8 + (lane & 3) * 2;
            float o00 = 2.f*acc[i][j][0] - cn[j][0];
            float o01 = 2.f*acc[i][j][1] - cn[j][1];
            float o10 = 2.f*acc[i][j][2] - cn[j][0];
            float o11 = 2.f*acc[i][j][3] - cn[j][1];
            m0 = fmaxf(m0, fmaxf(o00, o01));
            m8 = fmaxf(m8, fmaxf(o10, o11));
            __nv_bfloat162 v0 = __floats2bfloat162_rn(o00, o01);
            __nv_bfloat162 v1 = __floats2bfloat162_rn(o10, o11);
            *(__nv_bfloat162*)(g_negdist + (size_t)row0       * N_C + n) = v0;
            *(__nv_bfloat162*)(g_negdist + (size_t)(row0 + 8) * N_C + n) = v1;
        }
        m0 = fmaxf(m0, __shfl_xor_sync(0xffffffffu, m0, 1));
        m0 = fmaxf(m0, __shfl_xor_sync(0xffffffffu, m0, 2));
        m8 = fmaxf(m8, __shfl_xor_sync(0xffffffffu, m8, 1));
        m8 = fmaxf(m8, __shfl_xor_sync(0xffffffffu, m8, 2));
        if ((lane & 3) == 0) {
            int lr = wm * 64 + i * 16 + (lane >> 2);
            cm[lr][wn]     = m0;
            cm[lr + 8][wn] = m8;
        }
    }
    __syncthreads();
    if (tid < 256) {
        int r = tid >> 1, c = tid & 1;
        float m = fmaxf(cm[r][c*2], cm[r][c*2 + 1]);
        __nv_bfloat16 h = __float2bfloat16(m);   // rn: monotone, commutes with max
        unsigned short us = *(unsigned short*)&h;
        g_cmax[(size_t)(bm0 + r) * 2048 + (bn0 >> 6) + c] = (unsigned short)fkey16(us);
    }
}

// ---------------- kernel 3: top-96 via exact chunk-max pruning ----------------
#define TPK_T     512
#define TPK_NBUF  8192
#define TPK_NCAND 768
#define W_HIST  0        // 2048
#define W_PSUM  2048     // 512
#define W_HIST2 2560     // 32
#define W_EQ    2592     // 96
#define W_CLIST 2688     // 768
#define W_CMAX  3456     // 1024 words (2048 ushort)
#define W_BUFK  4480     // 4096 words (8192 ushort)
#define W_BUFI  8576     // 8192 words
#define TPK_SMEM ((8576 + 8192) * 4)   // 67072 B

__global__ __launch_bounds__(TPK_T)
void topk_kernel() {
    extern __shared__ unsigned tsm[];
    unsigned*       hist  = tsm + W_HIST;
    unsigned*       psum  = tsm + W_PSUM;
    unsigned*       hist2 = tsm + W_HIST2;
    int*            eqbuf = (int*)(tsm + W_EQ);
    int*            clist = (int*)(tsm + W_CLIST);
    unsigned short* cmx   = (unsigned short*)(tsm + W_CMAX);
    unsigned short* buf_k = (unsigned short*)(tsm + W_BUFK);
    int*            buf_i = (int*)(tsm + W_BUFI);
    __shared__ int sh_sel, sh_rem, cnt, cnt_gt, cnt_eq, ncand;
    __shared__ unsigned sh_thr;

    int row  = blockIdx.x;
    int tid  = threadIdx.x;
    int warp = tid >> 5, lane = tid & 31;
    const __nv_bfloat16* ndrow = g_negdist + (size_t)row * N_C;
    int* outi = g_idx + row * CTX;

    {
        const unsigned* gcm = (const unsigned*)(g_cmax + (size_t)row * 2048);
        for (int i = tid; i < 1024; i += TPK_T) tsm[W_CMAX + i] = gcm[i];
    }
    for (int i = tid; i < 2048; i += TPK_T) hist[i] = 0;
    if (tid < 32) hist2[tid] = 0;
    if (tid == 0) { cnt = 0; cnt_gt = 0; cnt_eq = 0; ncand = 0; }
    __syncthreads();

    for (int i = tid; i < 2048; i += TPK_T) atomicAdd(&hist[cmx[i] >> 5], 1u);
    __syncthreads();
    {
        int b0 = tid * 4;
        psum[tid] = hist[b0] + hist[b0+1] + hist[b0+2] + hist[b0+3];
    }
    __syncthreads();
    if (tid == 0) {
        int cum = 0, g;
        for (g = 511; g >= 0; g--) {
            if (cum + (int)psum[g] >= CTX) break;
            cum += (int)psum[g];
        }
        int d;
        for (d = 4*g + 3; d >= 4*g; d--) {
            if (cum + (int)hist[d] >= CTX) break;
            cum += (int)hist[d];
        }
        sh_sel = d;
        sh_rem = CTX - cum;
    }
    __syncthreads();
    {
        unsigned s1 = (unsigned)sh_sel;
        for (int i = tid; i < 2048; i += TPK_T)
            if ((cmx[i] >> 5) == s1) atomicAdd(&hist2[cmx[i] & 31u], 1u);
    }
    __syncthreads();
    if (tid == 0) {
        int need = sh_rem, cum = 0, d;
        for (d = 31; d >= 0; d--) {
            if (cum + (int)hist2[d] >= need) break;
            cum += (int)hist2[d];
        }
        sh_thr = ((unsigned)sh_sel << 5) | (unsigned)d;
    }
    __syncthreads();
    unsigned T = sh_thr;

    for (int i = tid; i < 2048; i += TPK_T) {
        if ((unsigned)cmx[i] >= T) {
            int p = atomicAdd(&ncand, 1);
            if (p < TPK_NCAND) clist[p] = i;
        }
    }
    __syncthreads();
    int nc = ncand;
    int mode = (nc <= TPK_NCAND) ? 0 : 1;

    if (mode == 0) {
        for (int ci = warp; ci < nc; ci += TPK_T / 32) {
            int ch = clist[ci];
            unsigned v = ((const unsigned*)(ndrow + ch * 64))[lane];
            #pragma unroll
            for (int h = 0; h < 2; h++) {
                unsigned u = fkey16((v >> (16*h)) & 0xffffu);
                bool take = u >= T;
                unsigned m = __ballot_sync(0xffffffffu, take);
                if (m) {
                    int ldr = __ffs(m) - 1;
                    int base = 0;
                    if (lane == ldr) base = atomicAdd(&cnt, __popc(m));
                    base = __shfl_sync(0xffffffffu, base, ldr);
                    if (take) {
                        int pos = base + __popc(m & ((1u << lane) - 1u));
                        if (pos < TPK_NBUF) {
                            buf_k[pos] = (unsigned short)u;
                            buf_i[pos] = ch * 64 + lane * 2 + h;
                        }
                    }
                }
            }
        }
        __syncthreads();
        if (cnt > TPK_NBUF) mode = 1;
        __syncthreads();
    }

    if (mode == 0) {
        int n = cnt;
        for (int i = tid; i < 2048; i += TPK_T) hist[i] = 0;
        if (tid < 32) hist2[tid] = 0;
        __syncthreads();
        for (int i = tid; i < n; i += TPK_T)
            atomicAdd(&hist[(unsigned)buf_k[i] >> 5], 1u);
        __syncthreads();
        {
            int b0 = tid * 4;
            psum[tid] = hist[b0] + hist[b0+1] + hist[b0+2] + hist[b0+3];
        }
        __syncthreads();
        if (tid == 0) {
            int cum = 0, g;
            for (g = 511; g >= 0; g--) {
                if (cum + (int)psum[g] >= CTX) break;
                cum += (int)psum[g];
            }
            int d;
            for (d = 4*g + 3; d >= 4*g; d--) {
                if (cum + (int)hist[d] >= CTX) break;
                cum += (int)hist[d];
            }
            sh_sel = d;
            sh_rem = CTX - cum;
        }
        __syncthreads();
        unsigned sel1 = (unsigned)sh_sel;
        int need = sh_rem;
        __syncthreads();

        for (int i = tid; i < n; i += TPK_T) {
            unsigned u = buf_k[i];
            unsigned bk = u >> 5;
            if (bk > sel1) {
                int pos = atomicAdd(&cnt_gt, 1);
                outi[pos] = buf_i[i];
            } else if (bk == sel1) {
                atomicAdd(&hist2[u & 31u], 1u);
            }
        }
        __syncthreads();
        if (tid == 0) {
            int cum = 0, d;
            for (d = 31; d >= 0; d--) {
                if (cum + (int)hist2[d] >= need) break;
                cum += (int)hist2[d];
            }
            sh_sel = d;
            sh_rem = need - cum;
        }
        __syncthreads();
        unsigned sel2 = (unsigned)sh_sel;
        for (int i = tid; i < n; i += TPK_T) {
            unsigned u = buf_k[i];
            if ((u >> 5) == sel1) {
                unsigned lo = u & 31u;
                if (lo > sel2) {
                    int pos = atomicAdd(&cnt_gt, 1);
                    outi[pos] = buf_i[i];
                } else if (lo == sel2) {
                    int pos = atomicAdd(&cnt_eq, 1);
                    if (pos < CTX) eqbuf[pos] = buf_i[i];
                }
            }
        }
        __syncthreads();
        if (tid < sh_rem) outi[cnt_gt + tid] = eqbuf[tid];
    } else {
        const uint4* nd4 = (const uint4*)ndrow;
        unsigned* fbuf = (unsigned*)buf_i;
        for (int i = tid; i < 2048; i += TPK_T) hist[i] = 0;
        if (tid < 32) hist2[tid] = 0;
        if (tid == 0) { cnt_gt = 0; cnt_eq = 0; }
        __syncthreads();

        #pragma unroll 2
        for (int i = tid; i < N_C / 8; i += TPK_T) {
            uint4 v = nd4[i];
            unsigned w[4] = {v.x, v.y, v.z, v.w};
            #pragma unroll
            for (int q = 0; q < 4; q++)
                #pragma unroll
                for (int h = 0; h < 2; h++) {
                    unsigned bucket = fkey16((w[q] >> (16*h)) & 0xffffu) >> 5;
                    unsigned m = __match_any_sync(0xffffffffu, bucket);
                    if (lane == (__ffs(m) - 1)) atomicAdd(&hist[bucket], __popc(m));
                }
        }
        __syncthreads();
        {
            int b0 = tid * 4;
            psum[tid] = hist[b0] + hist[b0+1] + hist[b0+2] + hist[b0+3];
        }
        __syncthreads();
        if (tid == 0) {
            int cum = 0, g;
            for (g = 511; g >= 0; g--) {
                if (cum + (int)psum[g] >= CTX) break;
                cum += (int)psum[g];
            }
            int d;
            for (d = 4*g + 3; d >= 4*g; d--) {
                if (cum + (int)hist[d] >= CTX) break;
                cum += (int)hist[d];
            }
            sh_sel = d;
            sh_rem = CTX - cum;
        }
        __syncthreads();
        unsigned sel1 = (unsigned)sh_sel;
        int need = sh_rem;
        __syncthreads();

        #pragma unroll 2
        for (int i = tid; i < N_C / 8; i += TPK_T) {
            uint4 v = nd4[i];
            unsigned w[4] = {v.x, v.y, v.z, v.w};
            #pragma unroll
            for (int q = 0; q < 4; q++)
                #pragma unroll
                for (int h = 0; h < 2; h++) {
                    unsigned u = fkey16((w[q] >> (16*h)) & 0xffffu);
                    unsigned bucket = u >> 5;
                    if (bucket > sel1) {
                        int pos = atomicAdd(&cnt_gt, 1);
                        outi[pos] = i * 8 + q * 2 + h;
                    } else if (bucket == sel1) {
                        int pos = atomicAdd(&cnt_eq, 1);
                        if (pos < TPK_NBUF)
                            fbuf[pos] = (unsigned)(i * 8 + q * 2 + h) * 32u + (u & 31u);
                    }
                }
        }
        __syncthreads();
        int neq = cnt_eq;
        if (neq <= TPK_NBUF) {
            for (int i = tid; i < neq; i += TPK_T) atomicAdd(&hist2[fbuf[i] & 31u], 1u);
            __syncthreads();
            if (tid == 0) {
                int cum = 0, d;
                for (d = 31; d >= 0; d--) {
                    if (cum + (int)hist2[d] >= need) break;
                    cum += (int)hist2[d];
                }
                sh_sel = d;
                sh_rem = need - cum;
                cnt_eq = 0;
            }
            __syncthreads();
            unsigned sel2 = (unsigned)sh_sel;
            for (int i = tid; i < neq; i += TPK_T) {
                unsigned e = fbuf[i];
                unsigned lo = e & 31u;
                if (lo > sel2) {
                    int pos = atomicAdd(&cnt_gt, 1);
                    outi[pos] = (int)(e >> 5);
                } else if (lo == sel2) {
                    int pos = atomicAdd(&cnt_eq, 1);
                    if (pos < CTX) eqbuf[pos] = (int)(e >> 5);
                }
            }
            __syncthreads();
            if (tid < sh_rem) outi[cnt_gt + tid] = eqbuf[tid];
        } else {
            #pragma unroll 1
            for (int i = tid; i < N_C / 8; i += TPK_T) {
                uint4 v = nd4[i];
                unsigned w[4] = {v.x, v.y, v.z, v.w};
                #pragma unroll
                for (int q = 0; q < 4; q++)
                    #pragma unroll
                    for (int h = 0; h < 2; h++) {
                        unsigned u = fkey16((w[q] >> (16*h)) & 0xffffu);
                        if ((u >> 5) == sel1) atomicAdd(&hist2[u & 31u], 1u);
                    }
            }
            __syncthreads();
            if (tid == 0) {
                int cum = 0, d;
                for (d = 31; d >= 0; d--) {
                    if (cum + (int)hist2[d] >= need) break;
                    cum += (int)hist2[d];
                }
                sh_sel = d;
                sh_rem = need - cum;
                cnt_eq = 0;
            }
            __syncthreads();
            unsigned thr = (sel1 << 5) | (unsigned)sh_sel;
            #pragma unroll 1
            for (int i = tid; i < N_C / 8; i += TPK_T) {
                uint4 v = nd4[i];
                unsigned w[4] = {v.x, v.y, v.z, v.w};
                #pragma unroll
                for (int q = 0; q < 4; q++)
                    #pragma unroll
                    for (int h = 0; h < 2; h++) {
                        unsigned u = fkey16((w[q] >> (16*h)) & 0xffffu);
                        if (u > thr && (u >> 5) == sel1) {
                            int pos = atomicAdd(&cnt_gt, 1);
                            outi[pos] = i * 8 + q * 2 + h;
                        } else if (u == thr) {
                            int pos = atomicAdd(&cnt_eq, 1);
                            if (pos < CTX) eqbuf[pos] = i * 8 + q * 2 + h;
                        }
                    }
            }
            __syncthreads();
            if (tid < sh_rem) outi[cnt_gt + tid] = eqbuf[tid];
        }
    }
}

// ---------------- kernel 4: attention + factored MLP (tf32 MMA, barrier-free mainloop) ----------------
// smem fp32-element layout (w1t staging REMOVED — B frags read direct from L2-resident W1):
#define F_CKS   0                      // ck fp32 [96][260]          = 24960
#define F_KS    24960                  // k row                      = 256
#define F_AS    25216                  // a[e]                       = 512
#define F_HB    25728                  // hbar[e]                    = 512
#define F_PR    26240                  // probs                      = 96
#define F_YV    26336                  // y values                   = 96
#define F_SIM   26432                  // sims                       = 96
#define F_CIDX  26528                  // int indices                = 96
#define F_ELEMS 26624
#define F_BYTES (F_ELEMS * 4)          // 106496 B

#define F_T 512

__global__ __launch_bounds__(F_T, 1)
void final_kernel(const float* __restrict__ X, const float* __restrict__ K,
                  const float* __restrict__ CK, const float* __restrict__ CY,
                  const float* __restrict__ WL, const float* __restrict__ BL,
                  const float* __restrict__ W1, const float* __restrict__ W2,
                  float* __restrict__ OUT) {
    extern __shared__ float sm[];
    float* cks   = sm + F_CKS;    // stride 260 (conflict-free frags)
    float* ks    = sm + F_KS;
    float* a_s   = sm + F_AS;
    float* hb    = sm + F_HB;
    float* probs = sm + F_PR;
    float* yv    = sm + F_YV;
    float* sims  = sm + F_SIM;
    int*   cidx  = (int*)(sm + F_CIDX);
    __shared__ float s_max, s_inv, s_sy;

    int b    = blockIdx.x;
    int tid  = threadIdx.x;
    int warp = tid >> 5, lane = tid & 31;
    int wm = warp >> 3, wn = warp & 7;       // 2 x 8 warp grid: M=48/warp, N=32/warp per nh
    int gq = lane >> 2, tg = lane & 3;

    // --- stage 0 ---
    if (tid < 256) ks[tid] = K[(size_t)b * DIM + tid];
    if (tid < CTX) {
        int ci = g_idx[b * CTX + tid];
        cidx[tid] = ci;
        yv[tid] = CY[ci];
        sims[tid] = 0.f;
    }
    hb[tid] = 0.f;
    a_s[tid] = g_a[(size_t)b * DB + tid];
    __syncthreads();

    // gather context_k fp32 -> cks, fused sim accumulation (fp32 exact)
    #pragma unroll 1
    for (int t = tid; t < CTX * 64; t += F_T) {
        int j  = t >> 6;
        int p4 = (t & 63) * 4;
        float4 v = *(const float4*)(CK + (size_t)cidx[j] * DIM + p4);
        *(float4*)(cks + j * 260 + p4) = v;
        float d0 = ks[p4]   - v.x, d1 = ks[p4+1] - v.y;
        float d2 = ks[p4+2] - v.z, d3 = ks[p4+3] - v.w;
        float s = d0*d0 + d1*d1 + d2*d2 + d3*d3;
        #pragma unroll
        for (int off = 16; off > 0; off >>= 1) s += __shfl_xor_sync(0xffffffffu, s, off);
        if (lane == 0) atomicAdd(&sims[j], -s);
    }
    __syncthreads();

    // --- stage 1: softmax (fp32 exact) ---
    if (tid == 0) {
        float m = sims[0];
        for (int j = 1; j < CTX; j++) m = fmaxf(m, sims[j]);
        s_max = m;
    }
    __syncthreads();
    if (tid < CTX) probs[tid] = expf(sims[tid] - s_max);
    __syncthreads();
    if (tid == 0) {
        float s = 0.f, sy = 0.f;
        for (int j = 0; j < CTX; j++) { s += probs[j]; sy += probs[j] * yv[j]; }
        s_inv = 1.f / s;
        s_sy  = sy / s;
    }
    __syncthreads();
    if (tid < CTX) probs[tid] *= s_inv;
    __syncthreads();

    // --- stage 2: barrier-free tf32 GEMM; B frags via LDG from L2-resident W1 ---
    #pragma unroll 1
    for (int nh = 0; nh < 2; nh++) {
        float acc[3][4][4];
        #pragma unroll
        for (int i = 0; i < 3; i++)
            #pragma unroll
            for (int jt = 0; jt < 4; jt++)
                #pragma unroll
                for (int r = 0; r < 4; r++) acc[i][jt][r] = 0.f;

        // warp's W1 row block for this nh: rows nh*256 + wn*32 + [0,32)
        const float* W1w = W1 + (size_t)(nh * 256 + wn * 32) * DIM;

        #pragma unroll 1
        for (int kc = 0; kc < 8; kc++) {
            #pragma unroll
            for (int s = 0; s < 4; s++) {
                int kk = kc * 32 + s * 8;
                unsigned af[3][4];
                #pragma unroll
                for (int i = 0; i < 3; i++) {
                    const float* ar = cks + (wm * 48 + i * 16 + gq) * 260 + kk + tg;
                    af[i][0] = __float_as_uint(ar[0]);
                    af[i][1] = __float_as_uint(ar[8 * 260]);
                    af[i][2] = __float_as_uint(ar[4]);
                    af[i][3] = __float_as_uint(ar[8 * 260 + 4]);
                }
                unsigned bfr[4][2];
                #pragma unroll
                for (int jt = 0; jt < 4; jt++) {
                    const float* br = W1w + (size_t)(jt * 8 + gq) * DIM + kk + tg;
                    bfr[jt][0] = __float_as_uint(__ldg(br));
                    bfr[jt][1] = __float_as_uint(__ldg(br + 4));
                }
                #pragma unroll
                for (int i = 0; i < 3; i++)
                    #pragma unroll
                    for (int jt = 0; jt < 4; jt++)
                        mma_tf32(acc[i][jt], af[i], bfr[jt]);
            }
        }

        // epilogue for this N-half
        #pragma unroll
        for (int jt = 0; jt < 4; jt++) {
            int e0 = nh * 256 + wn * 32 + jt * 8 + tg * 2;
            float a0 = a_s[e0], a1 = a_s[e0 + 1];
            float p0 = 0.f, p1 = 0.f;
            #pragma unroll
            for (int i = 0; i < 3; i++) {
                int r0 = wm * 48 + i * 16 + gq;
                float pr0 = probs[r0], pr1 = probs[r0 + 8];
                p0 += pr0 * fmaxf(a0 - acc[i][jt][0], 0.f)
                    + pr1 * fmaxf(a0 - acc[i][jt][2], 0.f);
                p1 += pr0 * fmaxf(a1 - acc[i][jt][1], 0.f)
                    + pr1 * fmaxf(a1 - acc[i][jt][3], 0.f);
            }
            atomicAdd(&hb[e0],     p0);
            atomicAdd(&hb[e0 + 1], p1);
        }
    }
    __syncthreads();

    // --- stage 3: out_d = x_d + sy*WL_d + BL_d + W2[d,:] . hbar ---
    if (tid < 256) {
        int d = tid;
        float val = X[(size_t)b * DIM + d] + s_sy * WL[d] + BL[d];
        const float4* w2r = (const float4*)(W2 + (size_t)d * DB);
        const float4* hb4 = (const float4*)hb;
        #pragma unroll 8
        for (int e4 = 0; e4 < DB / 4; e4++) {
            float4 w = w2r[e4];
            float4 h = hb4[e4];
            val += w.x*h.x + w.y*h.y + w.z*h.z + w.w*h.w;
        }
        OUT[(size_t)b * DIM + d] = val;
    }
}

// ---------------- launcher ----------------
extern "C" void kernel_launch(void* const* d_in, const int* in_sizes, int n_in,
                              void* d_out, int out_size) {
    const float* x  = (const float*)d_in[0];
    const float* k  = (const float*)d_in[1];
    const float* ck = (const float*)d_in[2];
    const float* cy = (const float*)d_in[3];
    const float* wl = (const float*)d_in[4];
    const float* bl = (const float*)d_in[5];
    const float* w1 = (const float*)d_in[6];
    const float* b1 = (const float*)d_in[7];
    const float* w2 = (const float*)d_in[8];
    float* out = (float*)d_out;

    // unconditional (no static guards; capture-legal)
    cudaFuncSetAttribute(final_kernel,
                         cudaFuncAttributeMaxDynamicSharedMemorySize, F_BYTES);
    cudaFuncSetAttribute(topk_kernel,
                         cudaFuncAttributeMaxDynamicSharedMemorySize, TPK_SMEM);

    __nv_bfloat16* kb  = nullptr;
    __nv_bfloat16* ckb = nullptr;
    cudaGetSymbolAddress((void**)&kb,  g_Kb);
    cudaGetSymbolAddress((void**)&ckb, g_CKb);

    conv_kernel<false><<<B_Q / 8, 256>>>(k,  kb);
    conv_kernel<true ><<<N_C / 8, 256>>>(ck, ckb);
    aker<<<dim3(B_Q / 64, DB / 64), 256>>>(k, w1, b1);
    dist_kernel<<<dim3(B_Q / 128, N_C / 128), 256>>>(kb, ckb);
    topk_kernel<<<B_Q, TPK_T, TPK_SMEM>>>();
    final_kernel<<<B_Q, F_T, F_BYTES>>>(x, k, ck, cy, wl, bl, w1, w2, out);
}

// round 17
// speedup vs baseline: 1.2969x; 1.2969x over previous
#include <cuda_runtime.h>
#include <cuda_bf16.h>
#include <cstdint>

#define B_Q   1024
#define N_C   131072
#define DIM   256
#define DB    512
#define CTX   96

// ---------------- device scratch (no dynamic allocations allowed) ----------------
__device__ float          g_cnorm[N_C];
__device__ __nv_bfloat16  g_negdist[(size_t)B_Q * N_C];     // 256 MB
__device__ unsigned short g_cmax[(size_t)B_Q * 2048];       // 4 MB: per-row per-64-chunk max key
__device__ __nv_bfloat16  g_CKb[(size_t)N_C * DIM];         // 67 MB
__device__ __nv_bfloat16  g_Kb[B_Q * DIM];                  // 512 KB
__device__ float          g_a[B_Q * DB];                    // 2 MB: a[q][e] = k_q.w1_e + b1_e
__device__ float          g_hbar[B_Q * DB];                 // 2 MB
__device__ float          g_sy[B_Q];
__device__ int            g_idx[B_Q * CTX];

// ================= helpers (legacy tensor path only — NO tcgen05) =================
__device__ __forceinline__ unsigned smem_u32(const void* p) {
    return (unsigned)__cvta_generic_to_shared(p);
}
__device__ __forceinline__ void cp16(void* sdst, const void* gsrc) {
    asm volatile("cp.async.cg.shared.global [%0], [%1], 16;\n"
                 :: "r"(smem_u32(sdst)), "l"(gsrc) : "memory");
}
#define CP_COMMIT() asm volatile("cp.async.commit_group;\n" ::: "memory")
#define CP_WAIT(n)  asm volatile("cp.async.wait_group %0;\n" :: "n"(n) : "memory")

__device__ __forceinline__ void mma16816(float* c, const unsigned* a, const unsigned* b) {
    asm volatile(
        "mma.sync.aligned.m16n8k16.row.col.f32.bf16.bf16.f32 "
        "{%0,%1,%2,%3}, {%4,%5,%6,%7}, {%8,%9}, {%0,%1,%2,%3};\n"
        : "+f"(c[0]), "+f"(c[1]), "+f"(c[2]), "+f"(c[3])
        : "r"(a[0]), "r"(a[1]), "r"(a[2]), "r"(a[3]), "r"(b[0]), "r"(b[1]));
}
__device__ __forceinline__ void mma_tf32(float* c, const unsigned* a, const unsigned* b) {
    asm volatile(
        "mma.sync.aligned.m16n8k8.row.col.f32.tf32.tf32.f32 "
        "{%0,%1,%2,%3}, {%4,%5,%6,%7}, {%8,%9}, {%0,%1,%2,%3};\n"
        : "+f"(c[0]), "+f"(c[1]), "+f"(c[2]), "+f"(c[3])
        : "r"(a[0]), "r"(a[1]), "r"(a[2]), "r"(a[3]), "r"(b[0]), "r"(b[1]));
}
__device__ __forceinline__ void ldsm_x4(unsigned* r, const __nv_bfloat16* p) {
    unsigned addr = smem_u32(p);
    asm volatile("ldmatrix.sync.aligned.m8n8.x4.shared.b16 {%0,%1,%2,%3}, [%4];\n"
                 : "=r"(r[0]), "=r"(r[1]), "=r"(r[2]), "=r"(r[3]) : "r"(addr));
}
__device__ __forceinline__ unsigned fkey16(unsigned h) {
    return (h & 0x8000u) ? (~h & 0xffffu) : (h | 0x8000u);  // monotonic in bf16 value
}

// ---------------- kernel 1: fp32 -> bf16 convert (+ optional norms) ----------------
template <bool WITH_NORM>
__global__ void conv_kernel(const float* __restrict__ src, __nv_bfloat16* __restrict__ dst) {
    int row  = blockIdx.x * 8 + (threadIdx.x >> 5);
    int lane = threadIdx.x & 31;
    const float4* p = (const float4*)(src + (size_t)row * DIM);
    float4 v0 = p[lane];
    float4 v1 = p[lane + 32];

    uint2* d2 = (uint2*)(dst + (size_t)row * DIM);
    __nv_bfloat162 a0 = __floats2bfloat162_rn(v0.x, v0.y);
    __nv_bfloat162 a1 = __floats2bfloat162_rn(v0.z, v0.w);
    __nv_bfloat162 a2 = __floats2bfloat162_rn(v1.x, v1.y);
    __nv_bfloat162 a3 = __floats2bfloat162_rn(v1.z, v1.w);
    d2[lane]      = make_uint2(*(unsigned*)&a0, *(unsigned*)&a1);
    d2[lane + 32] = make_uint2(*(unsigned*)&a2, *(unsigned*)&a3);

    if (WITH_NORM) {
        float s = v0.x*v0.x + v0.y*v0.y + v0.z*v0.z + v0.w*v0.w
                + v1.x*v1.x + v1.y*v1.y + v1.z*v1.z + v1.w*v1.w;
        #pragma unroll
        for (int off = 16; off > 0; off >>= 1) s += __shfl_xor_sync(0xffffffffu, s, off);
        if (lane == 0) g_cnorm[row] = s;
    }
}

// ---------------- kernel 1b: a[q][e] = k_q . w1_e + b1_e  (fp32, tiny GEMM) ----------------
__global__ __launch_bounds__(256)
void aker(const float* __restrict__ K, const float* __restrict__ W1,
          const float* __restrict__ B1) {
    __shared__ float Asm[16][65];
    __shared__ float Bsm[16][65];
    int tid = threadIdx.x;
    int tx = tid & 15, ty = tid >> 4;
    int bm0 = blockIdx.x * 64;
    int bn0 = blockIdx.y * 64;

    float acc[4][4];
    #pragma unroll
    for (int i = 0; i < 4; i++)
        #pragma unroll
        for (int j = 0; j < 4; j++) acc[i][j] = 0.f;

    int m  = tid >> 2;
    int k4 = (tid & 3) * 4;
    for (int kk = 0; kk < DIM; kk += 16) {
        float4 va = *(const float4*)(K  + (size_t)(bm0 + m) * DIM + kk + k4);
        Asm[k4][m] = va.x; Asm[k4+1][m] = va.y; Asm[k4+2][m] = va.z; Asm[k4+3][m] = va.w;
        float4 vb = *(const float4*)(W1 + (size_t)(bn0 + m) * DIM + kk + k4);
        Bsm[k4][m] = vb.x; Bsm[k4+1][m] = vb.y; Bsm[k4+2][m] = vb.z; Bsm[k4+3][m] = vb.w;
        __syncthreads();
        #pragma unroll
        for (int k = 0; k < 16; k++) {
            float a[4], b[4];
            #pragma unroll
            for (int i = 0; i < 4; i++) a[i] = Asm[k][ty*4 + i];
            #pragma unroll
            for (int j = 0; j < 4; j++) b[j] = Bsm[k][tx*4 + j];
            #pragma unroll
            for (int i = 0; i < 4; i++)
                #pragma unroll
                for (int j = 0; j < 4; j++) acc[i][j] += a[i] * b[j];
        }
        __syncthreads();
    }
    #pragma unroll
    for (int i = 0; i < 4; i++)
        #pragma unroll
        for (int j = 0; j < 4; j++)
            g_a[(size_t)(bm0 + ty*4 + i) * DB + bn0 + tx*4 + j] = acc[i][j] + B1[bn0 + tx*4 + j];
}

// ---------------- kernel 2: neg_dist (bf16 HMMA) + per-chunk max epilogue ----------------
#define SMS 40   // smem row stride in bf16 (80 B): conflict-free ldmatrix
__global__ __launch_bounds__(256, 2)
void dist_kernel(const __nv_bfloat16* __restrict__ Kb, const __nv_bfloat16* __restrict__ CKb) {
    __shared__ __align__(16) __nv_bfloat16 As[3][128 * SMS];
    __shared__ __align__(16) __nv_bfloat16 Bs[3][128 * SMS];
    __shared__ float cm[128][4];
    int tid  = threadIdx.x;
    int warp = tid >> 5, lane = tid & 31;
    int wm = warp >> 2, wn = warp & 3;       // 2 x 4 warps; warp tile 64(M) x 32(N)
    int bm0 = blockIdx.x * 128, bn0 = blockIdx.y * 128;

    float acc[4][4][4];
    #pragma unroll
    for (int i = 0; i < 4; i++)
        #pragma unroll
        for (int j = 0; j < 4; j++)
            #pragma unroll
            for (int r = 0; r < 4; r++) acc[i][j][r] = 0.f;

    auto load_chunk = [&](int kc, int b) {
        #pragma unroll
        for (int u = 0; u < 2; u++) {
            int t = u * 256 + tid;
            int r = t >> 2, c = (t & 3) * 8;
            cp16(As[b] + r * SMS + c, Kb  + (size_t)(bm0 + r) * DIM + kc * 32 + c);
            cp16(Bs[b] + r * SMS + c, CKb + (size_t)(bn0 + r) * DIM + kc * 32 + c);
        }
    };

    load_chunk(0, 0); CP_COMMIT();
    load_chunk(1, 1); CP_COMMIT();

    for (int kc = 0; kc < 8; kc++) {
        if (kc < 7) CP_WAIT(1); else CP_WAIT(0);
        __syncthreads();
        if (kc + 2 < 8) {
            load_chunk(kc + 2, (kc + 2) % 3);
            CP_COMMIT();
        }
        const __nv_bfloat16* Ac = As[kc % 3];
        const __nv_bfloat16* Bc = Bs[kc % 3];
        #pragma unroll
        for (int s = 0; s < 2; s++) {
            unsigned af[4][4], bf[2][4];
            #pragma unroll
            for (int i = 0; i < 4; i++) {
                int row = wm * 64 + i * 16 + (lane & 15);
                int col = s * 16 + (lane >> 4) * 8;
                ldsm_x4(af[i], Ac + row * SMS + col);
            }
            #pragma unroll
            for (int p = 0; p < 2; p++) {
                int mi   = lane >> 3;
                int nrow = wn * 32 + p * 16 + (mi >> 1) * 8 + (lane & 7);
                int kcol = s * 16 + (mi & 1) * 8;
                ldsm_x4(bf[p], Bc + nrow * SMS + kcol);
            }
            #pragma unroll
            for (int i = 0; i < 4; i++)
                #pragma unroll
                for (int j = 0; j < 4; j++)
                    mma16816(acc[i][j], af[i], &bf[j >> 1][(j & 1) * 2]);
        }
        __syncthreads();
    }

    float cn[4][2];
    #pragma unroll
    for (int j = 0; j < 4; j++) {
        int n = bn0 + wn * 32 + j * 8 + (lane & 3) * 2;
        cn[j][0] = g_cnorm[n]; cn[j][1] = g_cnorm[n + 1];
    }
    #pragma unroll
    for (int i = 0; i < 4; i++) {
        int row0 = bm0 + wm * 64 + i * 16 + (lane >> 2);
        float m0 = -3.4e38f, m8 = -3.4e38f;
        #pragma unroll
        for (int j = 0; j < 4; j++) {
            int n = bn0 + wn * 32 + j * 8 + (lane & 3) * 2;
            float o00 = 2.f*acc[i][j][0] - cn[j][0];
            float o01 = 2.f*acc[i][j][1] - cn[j][1];
            float o10 = 2.f*acc[i][j][2] - cn[j][0];
            float o11 = 2.f*acc[i][j][3] - cn[j][1];
            m0 = fmaxf(m0, fmaxf(o00, o01));
            m8 = fmaxf(m8, fmaxf(o10, o11));
            __nv_bfloat162 v0 = __floats2bfloat162_rn(o00, o01);
            __nv_bfloat162 v1 = __floats2bfloat162_rn(o10, o11);
            *(__nv_bfloat162*)(g_negdist + (size_t)row0       * N_C + n) = v0;
            *(__nv_bfloat162*)(g_negdist + (size_t)(row0 + 8) * N_C + n) = v1;
        }
        m0 = fmaxf(m0, __shfl_xor_sync(0xffffffffu, m0, 1));
        m0 = fmaxf(m0, __shfl_xor_sync(0xffffffffu, m0, 2));
        m8 = fmaxf(m8, __shfl_xor_sync(0xffffffffu, m8, 1));
        m8 = fmaxf(m8, __shfl_xor_sync(0xffffffffu, m8, 2));
        if ((lane & 3) == 0) {
            int lr = wm * 64 + i * 16 + (lane >> 2);
            cm[lr][wn]     = m0;
            cm[lr + 8][wn] = m8;
        }
    }
    __syncthreads();
    if (tid < 256) {
        int r = tid >> 1, c = tid & 1;
        float m = fmaxf(cm[r][c*2], cm[r][c*2 + 1]);
        __nv_bfloat16 h = __float2bfloat16(m);   // rn: monotone, commutes with max
        unsigned short us = *(unsigned short*)&h;
        g_cmax[(size_t)(bm0 + r) * 2048 + (bn0 >> 6) + c] = (unsigned short)fkey16(us);
    }
}

// ---------------- kernel 3: top-96 via exact chunk-max pruning ----------------
#define TPK_T     512
#define TPK_NBUF  8192
#define TPK_NCAND 768
#define W_HIST  0        // 2048
#define W_PSUM  2048     // 512
#define W_HIST2 2560     // 32
#define W_EQ    2592     // 96
#define W_CLIST 2688     // 768
#define W_CMAX  3456     // 1024 words (2048 ushort)
#define W_BUFK  4480     // 4096 words (8192 ushort)
#define W_BUFI  8576     // 8192 words
#define TPK_SMEM ((8576 + 8192) * 4)   // 67072 B

__global__ __launch_bounds__(TPK_T)
void topk_kernel() {
    extern __shared__ unsigned tsm[];
    unsigned*       hist  = tsm + W_HIST;
    unsigned*       psum  = tsm + W_PSUM;
    unsigned*       hist2 = tsm + W_HIST2;
    int*            eqbuf = (int*)(tsm + W_EQ);
    int*            clist = (int*)(tsm + W_CLIST);
    unsigned short* cmx   = (unsigned short*)(tsm + W_CMAX);
    unsigned short* buf_k = (unsigned short*)(tsm + W_BUFK);
    int*            buf_i = (int*)(tsm + W_BUFI);
    __shared__ int sh_sel, sh_rem, cnt, cnt_gt, cnt_eq, ncand;
    __shared__ unsigned sh_thr;

    int row  = blockIdx.x;
    int tid  = threadIdx.x;
    int warp = tid >> 5, lane = tid & 31;
    const __nv_bfloat16* ndrow = g_negdist + (size_t)row * N_C;
    int* outi = g_idx + row * CTX;

    {
        const unsigned* gcm = (const unsigned*)(g_cmax + (size_t)row * 2048);
        for (int i = tid; i < 1024; i += TPK_T) tsm[W_CMAX + i] = gcm[i];
    }
    for (int i = tid; i < 2048; i += TPK_T) hist[i] = 0;
    if (tid < 32) hist2[tid] = 0;
    if (tid == 0) { cnt = 0; cnt_gt = 0; cnt_eq = 0; ncand = 0; }
    __syncthreads();

    for (int i = tid; i < 2048; i += TPK_T) atomicAdd(&hist[cmx[i] >> 5], 1u);
    __syncthreads();
    {
        int b0 = tid * 4;
        psum[tid] = hist[b0] + hist[b0+1] + hist[b0+2] + hist[b0+3];
    }
    __syncthreads();
    if (tid == 0) {
        int cum = 0, g;
        for (g = 511; g >= 0; g--) {
            if (cum + (int)psum[g] >= CTX) break;
            cum += (int)psum[g];
        }
        int d;
        for (d = 4*g + 3; d >= 4*g; d--) {
            if (cum + (int)hist[d] >= CTX) break;
            cum += (int)hist[d];
        }
        sh_sel = d;
        sh_rem = CTX - cum;
    }
    __syncthreads();
    {
        unsigned s1 = (unsigned)sh_sel;
        for (int i = tid; i < 2048; i += TPK_T)
            if ((cmx[i] >> 5) == s1) atomicAdd(&hist2[cmx[i] & 31u], 1u);
    }
    __syncthreads();
    if (tid == 0) {
        int need = sh_rem, cum = 0, d;
        for (d = 31; d >= 0; d--) {
            if (cum + (int)hist2[d] >= need) break;
            cum += (int)hist2[d];
        }
        sh_thr = ((unsigned)sh_sel << 5) | (unsigned)d;
    }
    __syncthreads();
    unsigned T = sh_thr;

    for (int i = tid; i < 2048; i += TPK_T) {
        if ((unsigned)cmx[i] >= T) {
            int p = atomicAdd(&ncand, 1);
            if (p < TPK_NCAND) clist[p] = i;
        }
    }
    __syncthreads();
    int nc = ncand;
    int mode = (nc <= TPK_NCAND) ? 0 : 1;

    if (mode == 0) {
        for (int ci = warp; ci < nc; ci += TPK_T / 32) {
            int ch = clist[ci];
            unsigned v = ((const unsigned*)(ndrow + ch * 64))[lane];
            #pragma unroll
            for (int h = 0; h < 2; h++) {
                unsigned u = fkey16((v >> (16*h)) & 0xffffu);
                bool take = u >= T;
                unsigned m = __ballot_sync(0xffffffffu, take);
                if (m) {
                    int ldr = __ffs(m) - 1;
                    int base = 0;
                    if (lane == ldr) base = atomicAdd(&cnt, __popc(m));
                    base = __shfl_sync(0xffffffffu, base, ldr);
                    if (take) {
                        int pos = base + __popc(m & ((1u << lane) - 1u));
                        if (pos < TPK_NBUF) {
                            buf_k[pos] = (unsigned short)u;
                            buf_i[pos] = ch * 64 + lane * 2 + h;
                        }
                    }
                }
            }
        }
        __syncthreads();
        if (cnt > TPK_NBUF) mode = 1;
        __syncthreads();
    }

    if (mode == 0) {
        int n = cnt;
        for (int i = tid; i < 2048; i += TPK_T) hist[i] = 0;
        if (tid < 32) hist2[tid] = 0;
        __syncthreads();
        for (int i = tid; i < n; i += TPK_T)
            atomicAdd(&hist[(unsigned)buf_k[i] >> 5], 1u);
        __syncthreads();
        {
            int b0 = tid * 4;
            psum[tid] = hist[b0] + hist[b0+1] + hist[b0+2] + hist[b0+3];
        }
        __syncthreads();
        if (tid == 0) {
            int cum = 0, g;
            for (g = 511; g >= 0; g--) {
                if (cum + (int)psum[g] >= CTX) break;
                cum += (int)psum[g];
            }
            int d;
            for (d = 4*g + 3; d >= 4*g; d--) {
                if (cum + (int)hist[d] >= CTX) break;
                cum += (int)hist[d];
            }
            sh_sel = d;
            sh_rem = CTX - cum;
        }
        __syncthreads();
        unsigned sel1 = (unsigned)sh_sel;
        int need = sh_rem;
        __syncthreads();

        for (int i = tid; i < n; i += TPK_T) {
            unsigned u = buf_k[i];
            unsigned bk = u >> 5;
            if (bk > sel1) {
                int pos = atomicAdd(&cnt_gt, 1);
                outi[pos] = buf_i[i];
            } else if (bk == sel1) {
                atomicAdd(&hist2[u & 31u], 1u);
            }
        }
        __syncthreads();
        if (tid == 0) {
            int cum = 0, d;
            for (d = 31; d >= 0; d--) {
                if (cum + (int)hist2[d] >= need) break;
                cum += (int)hist2[d];
            }
            sh_sel = d;
            sh_rem = need - cum;
        }
        __syncthreads();
        unsigned sel2 = (unsigned)sh_sel;
        for (int i = tid; i < n; i += TPK_T) {
            unsigned u = buf_k[i];
            if ((u >> 5) == sel1) {
                unsigned lo = u & 31u;
                if (lo > sel2) {
                    int pos = atomicAdd(&cnt_gt, 1);
                    outi[pos] = buf_i[i];
                } else if (lo == sel2) {
                    int pos = atomicAdd(&cnt_eq, 1);
                    if (pos < CTX) eqbuf[pos] = buf_i[i];
                }
            }
        }
        __syncthreads();
        if (tid < sh_rem) outi[cnt_gt + tid] = eqbuf[tid];
    } else {
        const uint4* nd4 = (const uint4*)ndrow;
        unsigned* fbuf = (unsigned*)buf_i;
        for (int i = tid; i < 2048; i += TPK_T) hist[i] = 0;
        if (tid < 32) hist2[tid] = 0;
        if (tid == 0) { cnt_gt = 0; cnt_eq = 0; }
        __syncthreads();

        #pragma unroll 2
        for (int i = tid; i < N_C / 8; i += TPK_T) {
            uint4 v = nd4[i];
            unsigned w[4] = {v.x, v.y, v.z, v.w};
            #pragma unroll
            for (int q = 0; q < 4; q++)
                #pragma unroll
                for (int h = 0; h < 2; h++) {
                    unsigned bucket = fkey16((w[q] >> (16*h)) & 0xffffu) >> 5;
                    unsigned m = __match_any_sync(0xffffffffu, bucket);
                    if (lane == (__ffs(m) - 1)) atomicAdd(&hist[bucket], __popc(m));
                }
        }
        __syncthreads();
        {
            int b0 = tid * 4;
            psum[tid] = hist[b0] + hist[b0+1] + hist[b0+2] + hist[b0+3];
        }
        __syncthreads();
        if (tid == 0) {
            int cum = 0, g;
            for (g = 511; g >= 0; g--) {
                if (cum + (int)psum[g] >= CTX) break;
                cum += (int)psum[g];
            }
            int d;
            for (d = 4*g + 3; d >= 4*g; d--) {
                if (cum + (int)hist[d] >= CTX) break;
                cum += (int)hist[d];
            }
            sh_sel = d;
            sh_rem = CTX - cum;
        }
        __syncthreads();
        unsigned sel1 = (unsigned)sh_sel;
        int need = sh_rem;
        __syncthreads();

        #pragma unroll 2
        for (int i = tid; i < N_C / 8; i += TPK_T) {
            uint4 v = nd4[i];
            unsigned w[4] = {v.x, v.y, v.z, v.w};
            #pragma unroll
            for (int q = 0; q < 4; q++)
                #pragma unroll
                for (int h = 0; h < 2; h++) {
                    unsigned u = fkey16((w[q] >> (16*h)) & 0xffffu);
                    unsigned bucket = u >> 5;
                    if (bucket > sel1) {
                        int pos = atomicAdd(&cnt_gt, 1);
                        outi[pos] = i * 8 + q * 2 + h;
                    } else if (bucket == sel1) {
                        int pos = atomicAdd(&cnt_eq, 1);
                        if (pos < TPK_NBUF)
                            fbuf[pos] = (unsigned)(i * 8 + q * 2 + h) * 32u + (u & 31u);
                    }
                }
        }
        __syncthreads();
        int neq = cnt_eq;
        if (neq <= TPK_NBUF) {
            for (int i = tid; i < neq; i += TPK_T) atomicAdd(&hist2[fbuf[i] & 31u], 1u);
            __syncthreads();
            if (tid == 0) {
                int cum = 0, d;
                for (d = 31; d >= 0; d--) {
                    if (cum + (int)hist2[d] >= need) break;
                    cum += (int)hist2[d];
                }
                sh_sel = d;
                sh_rem = need - cum;
                cnt_eq = 0;
            }
            __syncthreads();
            unsigned sel2 = (unsigned)sh_sel;
            for (int i = tid; i < neq; i += TPK_T) {
                unsigned e = fbuf[i];
                unsigned lo = e & 31u;
                if (lo > sel2) {
                    int pos = atomicAdd(&cnt_gt, 1);
                    outi[pos] = (int)(e >> 5);
                } else if (lo == sel2) {
                    int pos = atomicAdd(&cnt_eq, 1);
                    if (pos < CTX) eqbuf[pos] = (int)(e >> 5);
                }
            }
            __syncthreads();
            if (tid < sh_rem) outi[cnt_gt + tid] = eqbuf[tid];
        } else {
            #pragma unroll 1
            for (int i = tid; i < N_C / 8; i += TPK_T) {
                uint4 v = nd4[i];
                unsigned w[4] = {v.x, v.y, v.z, v.w};
                #pragma unroll
                for (int q = 0; q < 4; q++)
                    #pragma unroll
                    for (int h = 0; h < 2; h++) {
                        unsigned u = fkey16((w[q] >> (16*h)) & 0xffffu);
                        if ((u >> 5) == sel1) atomicAdd(&hist2[u & 31u], 1u);
                    }
            }
            __syncthreads();
            if (tid == 0) {
                int cum = 0, d;
                for (d = 31; d >= 0; d--) {
                    if (cum + (int)hist2[d] >= need) break;
                    cum += (int)hist2[d];
                }
                sh_sel = d;
                sh_rem = need - cum;
                cnt_eq = 0;
            }
            __syncthreads();
            unsigned thr = (sel1 << 5) | (unsigned)sh_sel;
            #pragma unroll 1
            for (int i = tid; i < N_C / 8; i += TPK_T) {
                uint4 v = nd4[i];
                unsigned w[4] = {v.x, v.y, v.z, v.w};
                #pragma unroll
                for (int q = 0; q < 4; q++)
                    #pragma unroll
                    for (int h = 0; h < 2; h++) {
                        unsigned u = fkey16((w[q] >> (16*h)) & 0xffffu);
                        if (u > thr && (u >> 5) == sel1) {
                            int pos = atomicAdd(&cnt_gt, 1);
                            outi[pos] = i * 8 + q * 2 + h;
                        } else if (u == thr) {
                            int pos = atomicAdd(&cnt_eq, 1);
                            if (pos < CTX) eqbuf[pos] = i * 8 + q * 2 + h;
                        }
                    }
            }
            __syncthreads();
            if (tid < sh_rem) outi[cnt_gt + tid] = eqbuf[tid];
        }
    }
}

// ---------------- kernel 4: attention + factored MLP (tf32 MMA, smem-staged W1) ----------------
#define F_CKS   0                      // ck fp32 [96][260]          = 24960
#define F_W1T   24960                  // W1 tiles 2 x [256][36]     = 18432
#define F_KS    43392                  // k row                      = 256
#define F_AS    43648                  // a[e]                       = 512
#define F_HB    44160                  // hbar[e]                    = 512
#define F_PR    44672                  // probs                      = 96
#define F_YV    44768                  // y values                   = 96
#define F_SIM   44864                  // sims                       = 96
#define F_CIDX  44960                  // int indices                = 96
#define F_ELEMS 45056
#define F_BYTES (F_ELEMS * 4)          // 180224 B

#define F_T 512

__global__ __launch_bounds__(F_T, 1)
void final_kernel(const float* __restrict__ K, const float* __restrict__ CK,
                  const float* __restrict__ CY, const float* __restrict__ W1) {
    extern __shared__ float sm[];
    float* cks   = sm + F_CKS;    // stride 260 (conflict-free frags)
    float* w1t   = sm + F_W1T;    // 2 x [256][36]
    float* ks    = sm + F_KS;
    float* a_s   = sm + F_AS;
    float* hb    = sm + F_HB;
    float* probs = sm + F_PR;
    float* yv    = sm + F_YV;
    float* sims  = sm + F_SIM;
    int*   cidx  = (int*)(sm + F_CIDX);
    __shared__ float s_max, s_inv, s_sy;
    __shared__ float rpart[3], rpart2[3];

    int b    = blockIdx.x;
    int tid  = threadIdx.x;
    int warp = tid >> 5, lane = tid & 31;
    int wm = warp >> 3, wn = warp & 7;       // 2 x 8 warp grid
    int gq = lane >> 2, tg = lane & 3;

    // prefetch W1 tile (nh=0, kc=0) into buffer 0 — overlaps with gather below
    {
        #pragma unroll
        for (int u = 0; u < 4; u++) {
            int t2 = tid + u * F_T;
            int n = t2 >> 3, k8 = t2 & 7;
            cp16(w1t + n * 36 + k8 * 4, W1 + (size_t)n * DIM + k8 * 4);
        }
        CP_COMMIT();
    }

    // --- stage 0 ---
    if (tid < 256) ks[tid] = K[(size_t)b * DIM + tid];
    if (tid < CTX) {
        int ci = g_idx[b * CTX + tid];
        cidx[tid] = ci;
        yv[tid] = CY[ci];
        sims[tid] = 0.f;
    }
    hb[tid] = 0.f;
    a_s[tid] = g_a[(size_t)b * DB + tid];
    __syncthreads();

    // gather context_k fp32 -> cks, fused sim accumulation (fp32 exact)
    #pragma unroll 1
    for (int t = tid; t < CTX * 64; t += F_T) {
        int j  = t >> 6;
        int p4 = (t & 63) * 4;
        float4 v = *(const float4*)(CK + (size_t)cidx[j] * DIM + p4);
        *(float4*)(cks + j * 260 + p4) = v;
        float d0 = ks[p4]   - v.x, d1 = ks[p4+1] - v.y;
        float d2 = ks[p4+2] - v.z, d3 = ks[p4+3] - v.w;
        float s = d0*d0 + d1*d1 + d2*d2 + d3*d3;
        #pragma unroll
        for (int off = 16; off > 0; off >>= 1) s += __shfl_xor_sync(0xffffffffu, s, off);
        if (lane == 0) atomicAdd(&sims[j], -s);
    }
    __syncthreads();

    // --- stage 1: softmax (fp32, parallel reductions) ---
    if (tid < CTX) {
        float v = sims[tid];
        #pragma unroll
        for (int off = 16; off > 0; off >>= 1) v = fmaxf(v, __shfl_xor_sync(0xffffffffu, v, off));
        if (lane == 0) rpart[tid >> 5] = v;
    }
    __syncthreads();
    if (tid == 0) s_max = fmaxf(rpart[0], fmaxf(rpart[1], rpart[2]));
    __syncthreads();
    if (tid < CTX) probs[tid] = expf(sims[tid] - s_max);
    __syncthreads();
    if (tid < CTX) {
        float p = probs[tid], py = p * yv[tid];
        #pragma unroll
        for (int off = 16; off > 0; off >>= 1) {
            p  += __shfl_xor_sync(0xffffffffu, p, off);
            py += __shfl_xor_sync(0xffffffffu, py, off);
        }
        if (lane == 0) { rpart[tid >> 5] = p; rpart2[tid >> 5] = py; }
    }
    __syncthreads();
    if (tid == 0) {
        float s  = rpart[0] + rpart[1] + rpart[2];
        float sy = rpart2[0] + rpart2[1] + rpart2[2];
        s_inv = 1.f / s;
        s_sy  = sy / s;
        g_sy[b] = s_sy;
    }
    __syncthreads();
    if (tid < CTX) probs[tid] *= s_inv;
    __syncthreads();

    // --- stage 2: G[j][e] = ck_j . w1_e via tf32 mma; hbar_e = sum_j p_j relu(a_e - G) ---
    for (int nh = 0; nh < 2; nh++) {
        float acc[3][4][4];
        #pragma unroll
        for (int i = 0; i < 3; i++)
            #pragma unroll
            for (int jt = 0; jt < 4; jt++)
                #pragma unroll
                for (int r = 0; r < 4; r++) acc[i][jt][r] = 0.f;

        for (int kc = 0; kc < 8; kc++) {
            int gi = nh * 8 + kc;
            if (gi < 15) {
                int gn = gi + 1;
                int nh2 = gn >> 3, kc2 = gn & 7;
                float* wdst = w1t + (gn & 1) * 9216;
                #pragma unroll
                for (int u = 0; u < 4; u++) {
                    int t2 = tid + u * F_T;
                    int n = t2 >> 3, k8 = t2 & 7;
                    cp16(wdst + n * 36 + k8 * 4,
                         W1 + (size_t)(nh2 * 256 + n) * DIM + kc2 * 32 + k8 * 4);
                }
                CP_COMMIT();
                CP_WAIT(1);
            } else {
                CP_WAIT(0);
            }
            __syncthreads();
            const float* wb = w1t + (gi & 1) * 9216;
            #pragma unroll
            for (int s = 0; s < 4; s++) {
                int kk = kc * 32 + s * 8;
                unsigned af[3][4];
                #pragma unroll
                for (int i = 0; i < 3; i++) {
                    const float* ar = cks + (wm * 48 + i * 16 + gq) * 260 + kk + tg;
                    af[i][0] = __float_as_uint(ar[0]);
                    af[i][1] = __float_as_uint(ar[8 * 260]);
                    af[i][2] = __float_as_uint(ar[4]);
                    af[i][3] = __float_as_uint(ar[8 * 260 + 4]);
                }
                unsigned bfr[4][2];
                #pragma unroll
                for (int jt = 0; jt < 4; jt++) {
                    const float* br = wb + (wn * 32 + jt * 8 + gq) * 36 + s * 8 + tg;
                    bfr[jt][0] = __float_as_uint(br[0]);
                    bfr[jt][1] = __float_as_uint(br[4]);
                }
                #pragma unroll
                for (int i = 0; i < 3; i++)
                    #pragma unroll
                    for (int jt = 0; jt < 4; jt++)
                        mma_tf32(acc[i][jt], af[i], bfr[jt]);
            }
            __syncthreads();
        }

        // epilogue for this N-half
        #pragma unroll
        for (int jt = 0; jt < 4; jt++) {
            int e0 = nh * 256 + wn * 32 + jt * 8 + tg * 2;
            float a0 = a_s[e0], a1 = a_s[e0 + 1];
            float p0 = 0.f, p1 = 0.f;
            #pragma unroll
            for (int i = 0; i < 3; i++) {
                int r0 = wm * 48 + i * 16 + gq;
                float pr0 = probs[r0], pr1 = probs[r0 + 8];
                p0 += pr0 * fmaxf(a0 - acc[i][jt][0], 0.f)
                    + pr1 * fmaxf(a0 - acc[i][jt][2], 0.f);
                p1 += pr0 * fmaxf(a1 - acc[i][jt][1], 0.f)
                    + pr1 * fmaxf(a1 - acc[i][jt][3], 0.f);
            }
            atomicAdd(&hb[e0],     p0);
            atomicAdd(&hb[e0 + 1], p1);
        }
    }
    __syncthreads();

    // --- stage 3 moved to out_kernel: just spill hbar ---
    g_hbar[(size_t)b * DB + tid] = hb[tid];
}

// ---------------- kernel 5: OUT = X + sy*WL + BL + HBAR @ W2^T  (batched GEMM) ----------------
__global__ __launch_bounds__(256)
void out_kernel(const float* __restrict__ X, const float* __restrict__ WL,
                const float* __restrict__ BL, const float* __restrict__ W2,
                float* __restrict__ OUT) {
    __shared__ float Asm[16][65];
    __shared__ float Bsm[16][65];
    int tid = threadIdx.x;
    int tx = tid & 15, ty = tid >> 4;
    int bm0 = blockIdx.x * 64;   // query tile
    int bn0 = blockIdx.y * 64;   // d tile

    float acc[4][4];
    #pragma unroll
    for (int i = 0; i < 4; i++)
        #pragma unroll
        for (int j = 0; j < 4; j++) acc[i][j] = 0.f;

    int m  = tid >> 2;
    int k4 = (tid & 3) * 4;
    for (int kk = 0; kk < DB; kk += 16) {
        float4 va = *(const float4*)(g_hbar + (size_t)(bm0 + m) * DB + kk + k4);
        Asm[k4][m] = va.x; Asm[k4+1][m] = va.y; Asm[k4+2][m] = va.z; Asm[k4+3][m] = va.w;
        float4 vb = *(const float4*)(W2 + (size_t)(bn0 + m) * DB + kk + k4);
        Bsm[k4][m] = vb.x; Bsm[k4+1][m] = vb.y; Bsm[k4+2][m] = vb.z; Bsm[k4+3][m] = vb.w;
        __syncthreads();
        #pragma unroll
        for (int k = 0; k < 16; k++) {
            float a[4], bvals[4];
            #pragma unroll
            for (int i = 0; i < 4; i++) a[i] = Asm[k][ty*4 + i];
            #pragma unroll
            for (int j = 0; j < 4; j++) bvals[j] = Bsm[k][tx*4 + j];
            #pragma unroll
            for (int i = 0; i < 4; i++)
                #pragma unroll
                for (int j = 0; j < 4; j++) acc[i][j] += a[i] * bvals[j];
        }
        __syncthreads();
    }
    #pragma unroll
    for (int i = 0; i < 4; i++) {
        int q = bm0 + ty*4 + i;
        float sy = g_sy[q];
        #pragma unroll
        for (int j = 0; j < 4; j++) {
            int d = bn0 + tx*4 + j;
            OUT[(size_t)q * DIM + d] = acc[i][j] + X[(size_t)q * DIM + d] + sy * WL[d] + BL[d];
        }
    }
}

// ---------------- launcher ----------------
extern "C" void kernel_launch(void* const* d_in, const int* in_sizes, int n_in,
                              void* d_out, int out_size) {
    const float* x  = (const float*)d_in[0];
    const float* k  = (const float*)d_in[1];
    const float* ck = (const float*)d_in[2];
    const float* cy = (const float*)d_in[3];
    const float* wl = (const float*)d_in[4];
    const float* bl = (const float*)d_in[5];
    const float* w1 = (const float*)d_in[6];
    const float* b1 = (const float*)d_in[7];
    const float* w2 = (const float*)d_in[8];
    float* out = (float*)d_out;

    // unconditional (no static guards; capture-legal)
    cudaFuncSetAttribute(final_kernel,
                         cudaFuncAttributeMaxDynamicSharedMemorySize, F_BYTES);
    cudaFuncSetAttribute(topk_kernel,
                         cudaFuncAttributeMaxDynamicSharedMemorySize, TPK_SMEM);

    __nv_bfloat16* kb  = nullptr;
    __nv_bfloat16* ckb = nullptr;
    cudaGetSymbolAddress((void**)&kb,  g_Kb);
    cudaGetSymbolAddress((void**)&ckb, g_CKb);

    conv_kernel<false><<<B_Q / 8, 256>>>(k,  kb);
    conv_kernel<true ><<<N_C / 8, 256>>>(ck, ckb);
    aker<<<dim3(B_Q / 64, DB / 64), 256>>>(k, w1, b1);
    dist_kernel<<<dim3(B_Q / 128, N_C / 128), 256>>>(kb, ckb);
    topk_kernel<<<B_Q, TPK_T, TPK_SMEM>>>();
    final_kernel<<<B_Q, F_T, F_BYTES>>>(k, ck, cy, w1);
    out_kernel<<<dim3(B_Q / 64, DIM / 64), 256>>>(x, wl, bl, w2, out);
}